// round 16
// baseline (speedup 1.0000x reference)
#include <cuda_runtime.h>
#include <cuda_bf16.h>

#define TPB 256
#define V8PT 4                     // 256-bit vectors per thread per tile
#define TILE_V8 (TPB * V8PT)       // v8 vectors per tile = 1024 (128 KB)
#define CTAS 608                   // 152 SMs x 4 resident CTAs: single wave

// 256-bit global load/store (Blackwell sm_100+: LDG.E.256 / STG.E.256).
__device__ __forceinline__ void ldg256(const float* p, float* r) {
    asm volatile("ld.global.v8.f32 {%0,%1,%2,%3,%4,%5,%6,%7}, [%8];"
                 : "=f"(r[0]), "=f"(r[1]), "=f"(r[2]), "=f"(r[3]),
                   "=f"(r[4]), "=f"(r[5]), "=f"(r[6]), "=f"(r[7])
                 : "l"(p));
}
__device__ __forceinline__ void stg256(float* p, const float* r) {
    asm volatile("st.global.v8.f32 [%0], {%1,%2,%3,%4,%5,%6,%7,%8};"
                 :: "l"(p),
                    "f"(r[0]), "f"(r[1]), "f"(r[2]), "f"(r[3]),
                    "f"(r[4]), "f"(r[5]), "f"(r[6]), "f"(r[7])
                 : "memory");
}

// Persistent-CTA fused kernel, 256-bit accesses, block-contiguous tiles.
// Prologue (once per CTA): rebuild h_t = hadamard * signs[:,None] in shared,
// compute "is diagonal" flag via __syncthreads_or. Then each CTA loops over
// tiles tile = blockIdx.x, += gridDim.x (single wave, no wave transitions,
// one prologue per CTA instead of one per tile).
//  - diag path (this dataset): 4 front-batched LDG.E.256 + scale + STG.E.256
//    per tile; stores are fire-and-forget so next iteration's loads pipeline
//    right behind them.
//  - general fallback: per-float4 gather of the 16-elem tile + 4x16 dots.
//    Never executes for these inputs.
__global__ void __launch_bounds__(TPB, 4)
had_fused_kernel(const float* __restrict__ x, float* __restrict__ out,
                 const float* __restrict__ hadamard,
                 const float* __restrict__ signs, unsigned n_v8) {
    __shared__ float s_ht[256];
    __shared__ __align__(16) float s_diag[16];

    int t = threadIdx.x;
    int j = t >> 4;
    int i = t & 15;
    float v = hadamard[t] * signs[j];
    s_ht[t] = v;
    if (i == j) s_diag[j] = v;
    int offdiag = __syncthreads_or((i != j) && (v != 0.0f));

    unsigned n_tiles = (n_v8 + TILE_V8 - 1) / TILE_V8;

    if (!offdiag) {
        // Thread's diag half (8 floats), constant: all strides are even float4s.
        float d[8];
        #pragma unroll
        for (int q = 0; q < 8; ++q) d[q] = s_diag[(t & 1) * 8 + q];

        for (unsigned tile = blockIdx.x; tile < n_tiles; tile += CTAS) {
            unsigned base = tile * (unsigned)TILE_V8;       // v8 units
            unsigned h0 = base + (unsigned)t;
            const float* xp = x + (size_t)h0 * 8;
            float* op = out + (size_t)h0 * 8;

            if (base + TILE_V8 <= n_v8) {
                float a0[8], a1[8], a2[8], a3[8];
                ldg256(xp + 0 * TPB * 8, a0);
                ldg256(xp + 1 * TPB * 8, a1);
                ldg256(xp + 2 * TPB * 8, a2);
                ldg256(xp + 3 * TPB * 8, a3);
                #pragma unroll
                for (int q = 0; q < 8; ++q) a0[q] *= d[q];
                #pragma unroll
                for (int q = 0; q < 8; ++q) a1[q] *= d[q];
                #pragma unroll
                for (int q = 0; q < 8; ++q) a2[q] *= d[q];
                #pragma unroll
                for (int q = 0; q < 8; ++q) a3[q] *= d[q];
                stg256(op + 0 * TPB * 8, a0);
                stg256(op + 1 * TPB * 8, a1);
                stg256(op + 2 * TPB * 8, a2);
                stg256(op + 3 * TPB * 8, a3);
            } else {
                #pragma unroll
                for (int k = 0; k < V8PT; ++k) {
                    unsigned h = h0 + (unsigned)(k * TPB);
                    if (h < n_v8) {
                        float a[8];
                        ldg256(x + (size_t)h * 8, a);
                        #pragma unroll
                        for (int q = 0; q < 8; ++q) a[q] *= d[q];
                        stg256(out + (size_t)h * 8, a);
                    }
                }
            }
        }
    } else {
        // General fallback (correctness only): per-float4 outputs g = h*2+{0,1}.
        for (unsigned tile = blockIdx.x; tile < n_tiles; tile += CTAS) {
            unsigned h0 = tile * (unsigned)TILE_V8 + (unsigned)t;
            for (int k = 0; k < V8PT; ++k) {
                unsigned h = h0 + (unsigned)(k * TPB);
                if (h >= n_v8) continue;
                #pragma unroll
                for (int half = 0; half < 2; ++half) {
                    unsigned g = h * 2u + (unsigned)half;   // float4 index
                    const float* xt = x + (size_t)(g & ~3u) * 4;
                    float xv[16];
                    #pragma unroll
                    for (int ii = 0; ii < 16; ++ii) xv[ii] = xt[ii];
                    int seg = (int)(g & 3u);
                    float o[4];
                    #pragma unroll
                    for (int jj = 0; jj < 4; ++jj) {
                        int row = seg * 4 + jj;
                        float acc = 0.0f;
                        #pragma unroll
                        for (int ii = 0; ii < 16; ++ii)
                            acc = fmaf(xv[ii], s_ht[row * 16 + ii], acc);
                        o[jj] = acc;
                    }
                    float4* og = (float4*)(out + (size_t)g * 4);
                    *og = make_float4(o[0], o[1], o[2], o[3]);
                }
            }
        }
    }
}

extern "C" void kernel_launch(void* const* d_in, const int* in_sizes, int n_in,
                              void* d_out, int out_size) {
    const float* x        = (const float*)d_in[0];  // [4, 4096, 4096] f32
    const float* hadamard = (const float*)d_in[1];  // [16, 16] f32
    const float* signs    = (const float*)d_in[2];  // [16] f32
    float* out = (float*)d_out;

    unsigned n_v8 = (unsigned)(in_sizes[0] / 8);    // 256-bit vector count

    had_fused_kernel<<<CTAS, TPB>>>(x, out, hadamard, signs, n_v8);
}

// round 17
// speedup vs baseline: 1.1282x; 1.1282x over previous
#include <cuda_runtime.h>
#include <cuda_bf16.h>

#define TPB 256
#define V8PT 4                     // 256-bit vectors per thread
#define TILE_V8 (TPB * V8PT)       // v8 vectors per block = 1024 (128 KB)

// 256-bit global load/store (Blackwell sm_100+: LDG.E.256 / STG.E.256).
__device__ __forceinline__ void ldg256(const float* p, float* r) {
    asm volatile("ld.global.v8.f32 {%0,%1,%2,%3,%4,%5,%6,%7}, [%8];"
                 : "=f"(r[0]), "=f"(r[1]), "=f"(r[2]), "=f"(r[3]),
                   "=f"(r[4]), "=f"(r[5]), "=f"(r[6]), "=f"(r[7])
                 : "l"(p));
}
__device__ __forceinline__ void stg256(float* p, const float* r) {
    asm volatile("st.global.v8.f32 [%0], {%1,%2,%3,%4,%5,%6,%7,%8};"
                 :: "l"(p),
                    "f"(r[0]), "f"(r[1]), "f"(r[2]), "f"(r[3]),
                    "f"(r[4]), "f"(r[5]), "f"(r[6]), "f"(r[7])
                 : "memory");
}

// Single fused kernel, block-contiguous tiling, 256-bit accesses.
// (Measured champion: kernel 75.9us, DRAM 79.9% — HBM streaming ceiling for
// this 1:1 read:write f32 pattern. Persistent-CTA variant regressed: the
// grid launch's CTA scheduler provides cross-tile MLP for free.)
// Each block rebuilds h_t = hadamard * signs[:,None] in shared, computes an
// "is diagonal" flag via __syncthreads_or, then takes a grid-uniform branch:
//  - diag path (this dataset): block b owns 128KB window; thread t handles
//    v8 vectors t + k*256 (k=0..3), all 4 LDG.E.256 front-batched. Thread's
//    8-float span covers diag half (t & 1), constant per thread.
//  - general fallback: per-float4 gather of the 16-elem tile + 4x16 dots.
//    Never executes for these inputs.
__global__ void __launch_bounds__(TPB, 5)
had_fused_kernel(const float* __restrict__ x, float* __restrict__ out,
                 const float* __restrict__ hadamard,
                 const float* __restrict__ signs, unsigned n_v8) {
    __shared__ float s_ht[256];
    __shared__ __align__(16) float s_diag[16];

    int t = threadIdx.x;
    int j = t >> 4;
    int i = t & 15;
    float v = hadamard[t] * signs[j];
    s_ht[t] = v;
    if (i == j) s_diag[j] = v;
    int offdiag = __syncthreads_or((i != j) && (v != 0.0f));

    unsigned base = blockIdx.x * (unsigned)TILE_V8;   // in v8 units
    unsigned h0 = base + (unsigned)t;

    if (!offdiag) {
        // This thread's diag half (8 floats), constant since strides are even.
        float d[8];
        #pragma unroll
        for (int q = 0; q < 8; ++q) d[q] = s_diag[(t & 1) * 8 + q];

        const float* xp = x + (size_t)h0 * 8;
        float* op = out + (size_t)h0 * 8;

        if (base + TILE_V8 <= n_v8) {
            // Full-tile fast path: 4 x 256-bit loads front-batched.
            float a0[8], a1[8], a2[8], a3[8];
            ldg256(xp + 0 * TPB * 8, a0);
            ldg256(xp + 1 * TPB * 8, a1);
            ldg256(xp + 2 * TPB * 8, a2);
            ldg256(xp + 3 * TPB * 8, a3);
            #pragma unroll
            for (int q = 0; q < 8; ++q) a0[q] *= d[q];
            #pragma unroll
            for (int q = 0; q < 8; ++q) a1[q] *= d[q];
            #pragma unroll
            for (int q = 0; q < 8; ++q) a2[q] *= d[q];
            #pragma unroll
            for (int q = 0; q < 8; ++q) a3[q] *= d[q];
            stg256(op + 0 * TPB * 8, a0);
            stg256(op + 1 * TPB * 8, a1);
            stg256(op + 2 * TPB * 8, a2);
            stg256(op + 3 * TPB * 8, a3);
        } else {
            // Tail block: guarded per v8 vector.
            #pragma unroll
            for (int k = 0; k < V8PT; ++k) {
                unsigned h = h0 + (unsigned)(k * TPB);
                if (h < n_v8) {
                    float a[8];
                    ldg256(x + (size_t)h * 8, a);
                    #pragma unroll
                    for (int q = 0; q < 8; ++q) a[q] *= d[q];
                    stg256(out + (size_t)h * 8, a);
                }
            }
        }
    } else {
        // General fallback (correctness only): thread owns output float4
        // g = h*2 + {0,1}; tile base = g & ~3; row segment = g & 3.
        for (int k = 0; k < V8PT; ++k) {
            unsigned h = h0 + (unsigned)(k * TPB);
            if (h >= n_v8) continue;
            #pragma unroll
            for (int half = 0; half < 2; ++half) {
                unsigned g = h * 2u + (unsigned)half;   // float4 index
                const float* xt = x + (size_t)(g & ~3u) * 4;
                float xv[16];
                #pragma unroll
                for (int ii = 0; ii < 16; ++ii) xv[ii] = xt[ii];
                int seg = (int)(g & 3u);
                float o[4];
                #pragma unroll
                for (int jj = 0; jj < 4; ++jj) {
                    int row = seg * 4 + jj;
                    float acc = 0.0f;
                    #pragma unroll
                    for (int ii = 0; ii < 16; ++ii)
                        acc = fmaf(xv[ii], s_ht[row * 16 + ii], acc);
                    o[jj] = acc;
                }
                float4* og = (float4*)(out + (size_t)g * 4);
                *og = make_float4(o[0], o[1], o[2], o[3]);
            }
        }
    }
}

extern "C" void kernel_launch(void* const* d_in, const int* in_sizes, int n_in,
                              void* d_out, int out_size) {
    const float* x        = (const float*)d_in[0];  // [4, 4096, 4096] f32
    const float* hadamard = (const float*)d_in[1];  // [16, 16] f32
    const float* signs    = (const float*)d_in[2];  // [16] f32
    float* out = (float*)d_out;

    unsigned n_v8 = (unsigned)(in_sizes[0] / 8);    // 256-bit vector count

    int blocks = (int)((n_v8 + TILE_V8 - 1) / TILE_V8);
    had_fused_kernel<<<blocks, TPB>>>(x, out, hadamard, signs, n_v8);
}